// round 1
// baseline (speedup 1.0000x reference)
#include <cuda_runtime.h>
#include <cuda_bf16.h>

#define NN 10000
#define EE 160000
#define TEN 65536
#define EA (EE + NN)   // edges + self loops = 170000

// ---------------- scratch (static device globals; no allocation) ----------------
__device__ float g_xg[NN * 384];      // fc1 out
__device__ float g_h1[NN * 384];      // gat1 h = xg @ gat1_w
__device__ float g_gout1[NN * 384];   // gat1 aggregated
__device__ float g_hr1[NN * 384];     // relu(x + bn1)
__device__ float g_h5[NN * 256];      // fc5 out
__device__ float g_h2[NN * 256];      // gat2 h
__device__ float g_gout2[NN * 256];
__device__ float g_hr2[NN * 256];     // relu(h5 + bn2)
__device__ float g_hf[NN * 256];      // fc2 out

__device__ float g_as1[NN * 8], g_ad1[NN * 8], g_m1[NN * 8], g_dn1[NN * 8];
__device__ float g_as2[NN], g_ad2[NN], g_m2[NN], g_dn2[NN];
__device__ float g_sum1[384], g_ss1[384], g_mu1[384], g_rs1[384];
__device__ float g_sum2[256], g_ss2[256], g_mu2[256], g_rs2[256];

// ---------------- helpers ----------------
__device__ __forceinline__ void atomicMaxF(float* addr, float v) {
    if (v >= 0.f) atomicMax((int*)addr, __float_as_int(v));
    else          atomicMin((unsigned int*)addr, (unsigned int)__float_as_int(v));
}

__device__ __forceinline__ void edge_sd(const int* __restrict__ ei, int e, int& s, int& d) {
    if (e < EE) { s = ei[e]; d = ei[EE + e]; }
    else        { s = e - EE; d = e - EE; }
}

__device__ __forceinline__ float leaky(float v) { return v > 0.f ? v : 0.2f * v; }

// ---------------- GEMM: C[M,Nc] = A[M,K] @ B[K,Nc] (+ bias) ----------------
// BM=BN=64, BK=16, 16x16 threads, 4x4 per thread. Requires Nc%64==0, K%16==0.
__global__ void gemm64(const float* __restrict__ A, const float* __restrict__ B,
                       const float* __restrict__ bias, float* __restrict__ C,
                       int M, int K, int Nc) {
    __shared__ float As[16][64];
    __shared__ float Bs[16][64];
    const int tx = threadIdx.x, ty = threadIdx.y;
    const int t = ty * 16 + tx;
    const int m0 = blockIdx.y * 64, n0 = blockIdx.x * 64;
    const int la_m = t >> 2;          // 0..63
    const int la_k = (t & 3) * 4;     // 0,4,8,12
    const int lb_k = t >> 4;          // 0..15
    const int lb_n = (t & 15) * 4;    // 0..60
    const bool a_ok = (m0 + la_m) < M;
    float acc[4][4] = {};

    for (int k0 = 0; k0 < K; k0 += 16) {
        float4 av = a_ok ? *(const float4*)&A[(size_t)(m0 + la_m) * K + k0 + la_k]
                         : make_float4(0.f, 0.f, 0.f, 0.f);
        As[la_k + 0][la_m] = av.x; As[la_k + 1][la_m] = av.y;
        As[la_k + 2][la_m] = av.z; As[la_k + 3][la_m] = av.w;
        *(float4*)&Bs[lb_k][lb_n] =
            *(const float4*)&B[(size_t)(k0 + lb_k) * Nc + n0 + lb_n];
        __syncthreads();
#pragma unroll
        for (int kk = 0; kk < 16; kk++) {
            float4 a = *(const float4*)&As[kk][ty * 4];
            float4 b = *(const float4*)&Bs[kk][tx * 4];
            float ar[4] = {a.x, a.y, a.z, a.w};
            float br[4] = {b.x, b.y, b.z, b.w};
#pragma unroll
            for (int i = 0; i < 4; i++)
#pragma unroll
                for (int j = 0; j < 4; j++) acc[i][j] += ar[i] * br[j];
        }
        __syncthreads();
    }
#pragma unroll
    for (int i = 0; i < 4; i++) {
        int m = m0 + ty * 4 + i;
        if (m >= M) continue;
#pragma unroll
        for (int j = 0; j < 4; j++) {
            int n = n0 + tx * 4 + j;
            float v = acc[i][j] + (bias ? bias[n] : 0.f);
            C[(size_t)m * Nc + n] = v;
        }
    }
}

// ---------------- init kernels ----------------
__global__ void init1k() {
    int idx = blockIdx.x * blockDim.x + threadIdx.x;
    if (idx < NN * 384) g_gout1[idx] = 0.f;
    if (idx < NN * 8) { g_m1[idx] = __int_as_float(0xff800000); g_dn1[idx] = 0.f; }
    if (idx < 384) { g_sum1[idx] = 0.f; g_ss1[idx] = 0.f; }
}
__global__ void init2k() {
    int idx = blockIdx.x * blockDim.x + threadIdx.x;
    if (idx < NN * 256) g_gout2[idx] = 0.f;
    if (idx < NN) { g_m2[idx] = __int_as_float(0xff800000); g_dn2[idx] = 0.f; }
    if (idx < 256) { g_sum2[idx] = 0.f; g_ss2[idx] = 0.f; }
}

// ---------------- GAT1 (8 heads x 48 ch) ----------------
__global__ void coef1k(const float* __restrict__ asw, const float* __restrict__ adw) {
    int idx = blockIdx.x * blockDim.x + threadIdx.x;
    if (idx >= NN * 8) return;
    int n = idx >> 3, hd = idx & 7;
    const float* hp = g_h1 + (size_t)n * 384 + hd * 48;
    const float* aw = asw + hd * 48;
    const float* dw = adw + hd * 48;
    float s = 0.f, d = 0.f;
#pragma unroll
    for (int c = 0; c < 48; c++) { float v = hp[c]; s += v * aw[c]; d += v * dw[c]; }
    g_as1[idx] = s; g_ad1[idx] = d;
}

__global__ void emax1k(const int* __restrict__ ei) {
    int idx = blockIdx.x * blockDim.x + threadIdx.x;
    if (idx >= EA * 8) return;
    int e = idx >> 3, hd = idx & 7, s, d;
    edge_sd(ei, e, s, d);
    float v = leaky(g_as1[s * 8 + hd] + g_ad1[d * 8 + hd]);
    atomicMaxF(&g_m1[d * 8 + hd], v);
}

__global__ void esum1k(const int* __restrict__ ei) {
    int idx = blockIdx.x * blockDim.x + threadIdx.x;
    if (idx >= EA * 8) return;
    int e = idx >> 3, hd = idx & 7, s, d;
    edge_sd(ei, e, s, d);
    float v = leaky(g_as1[s * 8 + hd] + g_ad1[d * 8 + hd]);
    atomicAdd(&g_dn1[d * 8 + hd], __expf(v - g_m1[d * 8 + hd]));
}

__global__ void scat1k(const int* __restrict__ ei) {
    int gw = (blockIdx.x * blockDim.x + threadIdx.x) >> 5;
    if (gw >= EA) return;
    int lane = threadIdx.x & 31;
    int s, d;
    edge_sd(ei, gw, s, d);
    float al = 0.f;
    if (lane < 8) {
        float v = leaky(g_as1[s * 8 + lane] + g_ad1[d * 8 + lane]);
        al = __expf(v - g_m1[d * 8 + lane]) / (g_dn1[d * 8 + lane] + 1e-16f);
    }
    const float* hs = g_h1 + (size_t)s * 384;
    float* od = g_gout1 + (size_t)d * 384;
#pragma unroll
    for (int i = 0; i < 12; i++) {
        int c = lane + 32 * i;
        float a = __shfl_sync(0xffffffffu, al, c / 48);
        atomicAdd(&od[c], hs[c] * a);
    }
}

// ---------------- GAT2 (1 head x 256 ch) ----------------
__global__ void coef2k(const float* __restrict__ asw, const float* __restrict__ adw) {
    int gw = (blockIdx.x * blockDim.x + threadIdx.x) >> 5;
    if (gw >= NN) return;
    int lane = threadIdx.x & 31;
    const float* hp = g_h2 + (size_t)gw * 256;
    float s = 0.f, d = 0.f;
#pragma unroll
    for (int k = 0; k < 8; k++) {
        int c = lane + 32 * k;
        float v = hp[c];
        s += v * asw[c]; d += v * adw[c];
    }
#pragma unroll
    for (int off = 16; off; off >>= 1) {
        s += __shfl_down_sync(0xffffffffu, s, off);
        d += __shfl_down_sync(0xffffffffu, d, off);
    }
    if (lane == 0) { g_as2[gw] = s; g_ad2[gw] = d; }
}

__global__ void emax2k(const int* __restrict__ ei) {
    int e = blockIdx.x * blockDim.x + threadIdx.x;
    if (e >= EA) return;
    int s, d;
    edge_sd(ei, e, s, d);
    atomicMaxF(&g_m2[d], leaky(g_as2[s] + g_ad2[d]));
}

__global__ void esum2k(const int* __restrict__ ei) {
    int e = blockIdx.x * blockDim.x + threadIdx.x;
    if (e >= EA) return;
    int s, d;
    edge_sd(ei, e, s, d);
    float v = leaky(g_as2[s] + g_ad2[d]);
    atomicAdd(&g_dn2[d], __expf(v - g_m2[d]));
}

__global__ void scat2k(const int* __restrict__ ei) {
    int gw = (blockIdx.x * blockDim.x + threadIdx.x) >> 5;
    if (gw >= EA) return;
    int lane = threadIdx.x & 31;
    int s, d;
    edge_sd(ei, gw, s, d);
    float al = 0.f;
    if (lane == 0) {
        float v = leaky(g_as2[s] + g_ad2[d]);
        al = __expf(v - g_m2[d]) / (g_dn2[d] + 1e-16f);
    }
    al = __shfl_sync(0xffffffffu, al, 0);
    const float* hs = g_h2 + (size_t)s * 256;
    float* od = g_gout2 + (size_t)d * 256;
#pragma unroll
    for (int i = 0; i < 8; i++) {
        int c = lane + 32 * i;
        atomicAdd(&od[c], hs[c] * al);
    }
}

// ---------------- batch norm ----------------
__global__ void bn_partial(const float* __restrict__ X, int C,
                           float* __restrict__ sum, float* __restrict__ ss) {
    int col = blockIdx.x * 32 + threadIdx.x;
    float s = 0.f, q = 0.f;
    for (int r = threadIdx.y + blockIdx.y * 8; r < NN; r += 8 * gridDim.y) {
        float v = X[(size_t)r * C + col];
        s += v; q += v * v;
    }
    __shared__ float sh[8][32], sh2[8][32];
    sh[threadIdx.y][threadIdx.x] = s;
    sh2[threadIdx.y][threadIdx.x] = q;
    __syncthreads();
    if (threadIdx.y == 0) {
#pragma unroll
        for (int y = 1; y < 8; y++) { s += sh[y][threadIdx.x]; q += sh2[y][threadIdx.x]; }
        atomicAdd(&sum[col], s);
        atomicAdd(&ss[col], q);
    }
}

__global__ void bn_final(int C, const float* __restrict__ sum, const float* __restrict__ ss,
                         float* __restrict__ mu, float* __restrict__ rs) {
    int c = blockIdx.x * blockDim.x + threadIdx.x;
    if (c >= C) return;
    float m = sum[c] * (1.f / NN);
    float v = ss[c] * (1.f / NN) - m * m;
    mu[c] = m;
    rs[c] = rsqrtf(v + 1e-5f);
}

// h = relu(residual + (gat_out - mu)*rstd*gamma + beta)
// (gat bias dropped: batch_norm is exactly invariant to per-column constants)
__global__ void fuse1k(const float* __restrict__ x,
                       const float* __restrict__ g, const float* __restrict__ b) {
    int idx = blockIdx.x * blockDim.x + threadIdx.x;
    if (idx >= NN * 384) return;
    int c = idx % 384;
    float v = (g_gout1[idx] - g_mu1[c]) * g_rs1[c] * g[c] + b[c];
    float r = x[idx] + v;
    g_hr1[idx] = r > 0.f ? r : 0.f;
}

__global__ void fuse2k(const float* __restrict__ g, const float* __restrict__ b) {
    int idx = blockIdx.x * blockDim.x + threadIdx.x;
    if (idx >= NN * 256) return;
    int c = idx & 255;
    float v = (g_gout2[idx] - g_mu2[c]) * g_rs2[c] * g[c] + b[c];
    float r = g_h5[idx] + v;
    g_hr2[idx] = r > 0.f ? r : 0.f;
}

// ---------------- pair head: out[t] = (hf[s]*hf[d]) @ fc4_w + fc4_b ----------------
__global__ void pairk(const int* __restrict__ ei, const int* __restrict__ tid,
                      const float* __restrict__ w4, const float* __restrict__ b4,
                      float* __restrict__ out) {
    int gw = (blockIdx.x * blockDim.x + threadIdx.x) >> 5;
    if (gw >= TEN) return;
    int lane = threadIdx.x & 31;
    int e = tid[gw];
    int s = ei[e], d = ei[EE + e];
    const float* hs = g_hf + (size_t)s * 256;
    const float* hd = g_hf + (size_t)d * 256;
    float acc[7] = {};
#pragma unroll
    for (int k = 0; k < 8; k++) {
        int c = lane + 32 * k;
        float p = hs[c] * hd[c];
        const float* wr = &w4[c * 7];
#pragma unroll
        for (int j = 0; j < 7; j++) acc[j] += p * wr[j];
    }
#pragma unroll
    for (int j = 0; j < 7; j++)
#pragma unroll
        for (int off = 16; off; off >>= 1)
            acc[j] += __shfl_down_sync(0xffffffffu, acc[j], off);
    if (lane == 0) {
#pragma unroll
        for (int j = 0; j < 7; j++) out[(size_t)gw * 7 + j] = acc[j] + b4[j];
    }
}

// ---------------- launch ----------------
extern "C" void kernel_launch(void* const* d_in, const int* in_sizes, int n_in,
                              void* d_out, int out_size) {
    const float* x       = (const float*)d_in[0];
    const int*   ei      = (const int*)d_in[1];
    const int*   teid    = (const int*)d_in[2];
    const float* fc1_w   = (const float*)d_in[3];
    const float* fc1_b   = (const float*)d_in[4];
    const float* fc5_w   = (const float*)d_in[5];
    const float* fc5_b   = (const float*)d_in[6];
    const float* fc2_w   = (const float*)d_in[7];
    const float* fc2_b   = (const float*)d_in[8];
    const float* fc4_w   = (const float*)d_in[9];
    const float* fc4_b   = (const float*)d_in[10];
    const float* gat1_w  = (const float*)d_in[11];
    const float* gat1_as = (const float*)d_in[12];
    const float* gat1_ad = (const float*)d_in[13];
    /* gat1_b d_in[14] unused: BN-invariant */
    const float* gat2_w  = (const float*)d_in[15];
    const float* gat2_as = (const float*)d_in[16];
    const float* gat2_ad = (const float*)d_in[17];
    /* gat2_b d_in[18] unused: BN-invariant */
    const float* bn1_g   = (const float*)d_in[19];
    const float* bn1_b   = (const float*)d_in[20];
    const float* bn2_g   = (const float*)d_in[21];
    const float* bn2_b   = (const float*)d_in[22];
    float* out = (float*)d_out;

    float *p_xg, *p_h1, *p_hr1, *p_h5, *p_h2, *p_hr2, *p_hf, *p_gout1, *p_gout2;
    float *p_sum1, *p_ss1, *p_mu1, *p_rs1, *p_sum2, *p_ss2, *p_mu2, *p_rs2;
    cudaGetSymbolAddress((void**)&p_xg, g_xg);
    cudaGetSymbolAddress((void**)&p_h1, g_h1);
    cudaGetSymbolAddress((void**)&p_hr1, g_hr1);
    cudaGetSymbolAddress((void**)&p_h5, g_h5);
    cudaGetSymbolAddress((void**)&p_h2, g_h2);
    cudaGetSymbolAddress((void**)&p_hr2, g_hr2);
    cudaGetSymbolAddress((void**)&p_hf, g_hf);
    cudaGetSymbolAddress((void**)&p_gout1, g_gout1);
    cudaGetSymbolAddress((void**)&p_gout2, g_gout2);
    cudaGetSymbolAddress((void**)&p_sum1, g_sum1);
    cudaGetSymbolAddress((void**)&p_ss1, g_ss1);
    cudaGetSymbolAddress((void**)&p_mu1, g_mu1);
    cudaGetSymbolAddress((void**)&p_rs1, g_rs1);
    cudaGetSymbolAddress((void**)&p_sum2, g_sum2);
    cudaGetSymbolAddress((void**)&p_ss2, g_ss2);
    cudaGetSymbolAddress((void**)&p_mu2, g_mu2);
    cudaGetSymbolAddress((void**)&p_rs2, g_rs2);

    dim3 tb(16, 16);
    const int MB = (NN + 63) / 64;  // 157

    // fc1: xg = x @ fc1_w + b
    gemm64<<<dim3(6, MB), tb>>>(x, fc1_w, fc1_b, p_xg, NN, 384, 384);
    // gat1 h = xg @ gat1_w
    gemm64<<<dim3(6, MB), tb>>>(p_xg, gat1_w, nullptr, p_h1, NN, 384, 384);

    init1k<<<(NN * 384 + 255) / 256, 256>>>();
    coef1k<<<(NN * 8 + 255) / 256, 256>>>(gat1_as, gat1_ad);
    emax1k<<<(EA * 8 + 255) / 256, 256>>>(ei);
    esum1k<<<(EA * 8 + 255) / 256, 256>>>(ei);
    scat1k<<<(EA * 32 + 255) / 256, 256>>>(ei);

    bn_partial<<<dim3(12, 16), dim3(32, 8)>>>(p_gout1, 384, p_sum1, p_ss1);
    bn_final<<<2, 256>>>(384, p_sum1, p_ss1, p_mu1, p_rs1);
    fuse1k<<<(NN * 384 + 255) / 256, 256>>>(x, bn1_g, bn1_b);

    // fc5
    gemm64<<<dim3(4, MB), tb>>>(p_hr1, fc5_w, fc5_b, p_h5, NN, 384, 256);
    // gat2 h
    gemm64<<<dim3(4, MB), tb>>>(p_h5, gat2_w, nullptr, p_h2, NN, 256, 256);

    init2k<<<(NN * 256 + 255) / 256, 256>>>();
    coef2k<<<(NN * 32 + 255) / 256, 256>>>(gat2_as, gat2_ad);
    emax2k<<<(EA + 255) / 256, 256>>>(ei);
    esum2k<<<(EA + 255) / 256, 256>>>(ei);
    scat2k<<<(EA * 32 + 255) / 256, 256>>>(ei);

    bn_partial<<<dim3(8, 16), dim3(32, 8)>>>(p_gout2, 256, p_sum2, p_ss2);
    bn_final<<<1, 256>>>(256, p_sum2, p_ss2, p_mu2, p_rs2);
    fuse2k<<<(NN * 256 + 255) / 256, 256>>>(bn2_g, bn2_b);

    // fc2
    gemm64<<<dim3(4, MB), tb>>>(p_hr2, fc2_w, fc2_b, p_hf, NN, 256, 256);

    // pair head
    pairk<<<(TEN * 32 + 255) / 256, 256>>>(ei, teid, fc4_w, fc4_b, out);
}

// round 2
// speedup vs baseline: 1.7302x; 1.7302x over previous
#include <cuda_runtime.h>
#include <cuda_bf16.h>
#include <cstdint>

#define NN 10000
#define EE 160000
#define TEN 65536
#define EA (EE + NN)   // edges + self loops = 170000

// ---------------- scratch (static device globals; no allocation) ----------------
__device__ float g_w1c[384 * 384];    // fc1_w @ gat1_w
__device__ float g_b1c[384];          // fc1_b @ gat1_w
__device__ float g_h1[NN * 384];      // gat1 h = x @ w1c + b1c
__device__ float g_num1[NN * 384];    // gat1 unnormalized aggregate
__device__ float g_hr1[NN * 384];     // relu(x + bn1)
__device__ float g_h5[NN * 256];      // fc5 out
__device__ float g_h2[NN * 256];      // gat2 h
__device__ float g_num2[NN * 256];
__device__ float g_hr2[NN * 256];     // relu(h5 + bn2)
__device__ float g_hf[NN * 256];      // fc2 out

__device__ float g_as1[NN * 8], g_ad1[NN * 8], g_dn1[NN * 8];   // dn becomes 1/den after invk
__device__ float g_as2[NN], g_ad2[NN], g_dn2[NN];
__device__ float g_sum1[384], g_ss1[384], g_mu1[384], g_rs1[384];
__device__ float g_sum2[256], g_ss2[256], g_mu2[256], g_rs2[256];

// ---------------- helpers ----------------
__device__ __forceinline__ void edge_sd(const int* __restrict__ ei, int e, int& s, int& d) {
    if (e < EE) { s = ei[e]; d = ei[EE + e]; }
    else        { s = e - EE; d = e - EE; }
}

__device__ __forceinline__ float leaky(float v) { return v > 0.f ? v : 0.2f * v; }

__device__ __forceinline__ uint32_t f2tf32(float v) {
    uint32_t u;
    asm("cvt.rna.tf32.f32 %0, %1;" : "=r"(u) : "f"(v));
    return u;
}

// ---------------- TF32 tensor-core GEMM: C[M,Nc] = A[M,K] @ B[K,Nc] (+bias) --
// 128x128 block tile, BK=32, 256 threads (8 warps, 2x4), warp tile 64x32.
// Requires K%32==0, Nc%128==0. M tail guarded.
__global__ void __launch_bounds__(256) gemm_tf32(
    const float* __restrict__ A, const float* __restrict__ B,
    const float* __restrict__ bias, float* __restrict__ C,
    int M, int K, int Nc)
{
    __shared__ uint32_t As[128 * 36];   // [m][k] padded 32->36 : conflict-free frags
    __shared__ uint32_t Bs[32 * 136];   // [k][n] padded 128->136 : conflict-free frags
    const int t = threadIdx.x, lane = t & 31, wid = t >> 5;
    const int wm = (wid & 1) * 64, wn = (wid >> 1) * 32;
    const int m0 = blockIdx.y * 128, n0 = blockIdx.x * 128;
    float acc[4][4][4];
#pragma unroll
    for (int i = 0; i < 4; i++)
#pragma unroll
        for (int j = 0; j < 4; j++)
#pragma unroll
            for (int q = 0; q < 4; q++) acc[i][j][q] = 0.f;

    for (int k0 = 0; k0 < K; k0 += 32) {
        // stage A tile (convert to tf32)
#pragma unroll
        for (int j = 0; j < 4; j++) {
            int idx = t + 256 * j;
            int row = idx >> 3, kc = (idx & 7) * 4;
            float4 v = make_float4(0.f, 0.f, 0.f, 0.f);
            if (m0 + row < M)
                v = *(const float4*)&A[(size_t)(m0 + row) * K + k0 + kc];
            uint4 u = make_uint4(f2tf32(v.x), f2tf32(v.y), f2tf32(v.z), f2tf32(v.w));
            *(uint4*)&As[row * 36 + kc] = u;
        }
        // stage B tile
#pragma unroll
        for (int j = 0; j < 4; j++) {
            int idx = t + 256 * j;
            int kr = idx >> 5, nc = (idx & 31) * 4;
            float4 v = *(const float4*)&B[(size_t)(k0 + kr) * Nc + n0 + nc];
            uint4 u = make_uint4(f2tf32(v.x), f2tf32(v.y), f2tf32(v.z), f2tf32(v.w));
            *(uint4*)&Bs[kr * 136 + nc] = u;
        }
        __syncthreads();
#pragma unroll
        for (int ks = 0; ks < 4; ks++) {
            uint32_t af[4][4], bf[4][2];
            const int kk = ks * 8 + (lane & 3);
#pragma unroll
            for (int mt = 0; mt < 4; mt++) {
                int m = wm + mt * 16 + (lane >> 2);
                af[mt][0] = As[m * 36 + kk];
                af[mt][1] = As[(m + 8) * 36 + kk];
                af[mt][2] = As[m * 36 + kk + 4];
                af[mt][3] = As[(m + 8) * 36 + kk + 4];
            }
#pragma unroll
            for (int nt = 0; nt < 4; nt++) {
                int n = wn + nt * 8 + (lane >> 2);
                bf[nt][0] = Bs[kk * 136 + n];
                bf[nt][1] = Bs[(kk + 4) * 136 + n];
            }
#pragma unroll
            for (int mt = 0; mt < 4; mt++)
#pragma unroll
                for (int nt = 0; nt < 4; nt++) {
                    asm volatile(
                        "mma.sync.aligned.m16n8k8.row.col.f32.tf32.tf32.f32 "
                        "{%0,%1,%2,%3}, {%4,%5,%6,%7}, {%8,%9}, {%0,%1,%2,%3};\n"
                        : "+f"(acc[mt][nt][0]), "+f"(acc[mt][nt][1]),
                          "+f"(acc[mt][nt][2]), "+f"(acc[mt][nt][3])
                        : "r"(af[mt][0]), "r"(af[mt][1]), "r"(af[mt][2]), "r"(af[mt][3]),
                          "r"(bf[nt][0]), "r"(bf[nt][1]));
                }
        }
        __syncthreads();
    }
    // epilogue
#pragma unroll
    for (int mt = 0; mt < 4; mt++) {
#pragma unroll
        for (int nt = 0; nt < 4; nt++) {
            int r = m0 + wm + mt * 16 + (lane >> 2);
            int c = n0 + wn + nt * 8 + 2 * (lane & 3);
            float b0 = bias ? bias[c] : 0.f;
            float b1 = bias ? bias[c + 1] : 0.f;
            if (r < M) {
                float2 v = make_float2(acc[mt][nt][0] + b0, acc[mt][nt][1] + b1);
                *(float2*)&C[(size_t)r * Nc + c] = v;
            }
            if (r + 8 < M) {
                float2 v = make_float2(acc[mt][nt][2] + b0, acc[mt][nt][3] + b1);
                *(float2*)&C[(size_t)(r + 8) * Nc + c] = v;
            }
        }
    }
}

// ---------------- small fp32 GEMM (for 384x384x384 weight-fuse) ----------------
__global__ void gemm64(const float* __restrict__ A, const float* __restrict__ B,
                       const float* __restrict__ bias, float* __restrict__ C,
                       int M, int K, int Nc) {
    __shared__ float As[16][64];
    __shared__ float Bs[16][64];
    const int tx = threadIdx.x, ty = threadIdx.y;
    const int t = ty * 16 + tx;
    const int m0 = blockIdx.y * 64, n0 = blockIdx.x * 64;
    const int la_m = t >> 2;
    const int la_k = (t & 3) * 4;
    const int lb_k = t >> 4;
    const int lb_n = (t & 15) * 4;
    const bool a_ok = (m0 + la_m) < M;
    float acc[4][4] = {};
    for (int k0 = 0; k0 < K; k0 += 16) {
        float4 av = a_ok ? *(const float4*)&A[(size_t)(m0 + la_m) * K + k0 + la_k]
                         : make_float4(0.f, 0.f, 0.f, 0.f);
        As[la_k + 0][la_m] = av.x; As[la_k + 1][la_m] = av.y;
        As[la_k + 2][la_m] = av.z; As[la_k + 3][la_m] = av.w;
        *(float4*)&Bs[lb_k][lb_n] =
            *(const float4*)&B[(size_t)(k0 + lb_k) * Nc + n0 + lb_n];
        __syncthreads();
#pragma unroll
        for (int kk = 0; kk < 16; kk++) {
            float4 a = *(const float4*)&As[kk][ty * 4];
            float4 b = *(const float4*)&Bs[kk][tx * 4];
            float ar[4] = {a.x, a.y, a.z, a.w};
            float br[4] = {b.x, b.y, b.z, b.w};
#pragma unroll
            for (int i = 0; i < 4; i++)
#pragma unroll
                for (int j = 0; j < 4; j++) acc[i][j] += ar[i] * br[j];
        }
        __syncthreads();
    }
#pragma unroll
    for (int i = 0; i < 4; i++) {
        int m = m0 + ty * 4 + i;
        if (m >= M) continue;
#pragma unroll
        for (int j = 0; j < 4; j++) {
            int n = n0 + tx * 4 + j;
            C[(size_t)m * Nc + n] = acc[i][j] + (bias ? bias[n] : 0.f);
        }
    }
}

// b1c[j] = sum_k fc1_b[k] * gat1_w[k][j]
__global__ void biascomb(const float* __restrict__ fb, const float* __restrict__ W) {
    int j = blockIdx.x * blockDim.x + threadIdx.x;
    if (j >= 384) return;
    float s = 0.f;
    for (int k = 0; k < 384; k++) s += fb[k] * W[k * 384 + j];
    g_b1c[j] = s;
}

// ---------------- init ----------------
__global__ void init1k() {
    int idx = blockIdx.x * blockDim.x + threadIdx.x;
    if (idx < NN * 384) g_num1[idx] = 0.f;
    if (idx < NN * 8) g_dn1[idx] = 0.f;
    if (idx < 384) { g_sum1[idx] = 0.f; g_ss1[idx] = 0.f; }
}
__global__ void init2k() {
    int idx = blockIdx.x * blockDim.x + threadIdx.x;
    if (idx < NN * 256) g_num2[idx] = 0.f;
    if (idx < NN) g_dn2[idx] = 0.f;
    if (idx < 256) { g_sum2[idx] = 0.f; g_ss2[idx] = 0.f; }
}

// ---------------- GAT1 coefficients (warp per node, float4 coalesced) ----------
__global__ void coef1k(const float* __restrict__ asw, const float* __restrict__ adw) {
    __shared__ float sacc[8][16];
    int t = threadIdx.x, lane = t & 31, w = t >> 5;
    int n = blockIdx.x * 8 + w;
    if (lane < 16) sacc[w][lane] = 0.f;
    __syncwarp();
    if (n < NN) {
        const float4* hp = (const float4*)(g_h1 + (size_t)n * 384);
        const float4* ap = (const float4*)asw;   // a_src is (8,48) flat == h chunk layout
        const float4* dp = (const float4*)adw;
#pragma unroll
        for (int i = 0; i < 3; i++) {
            int c4 = lane + 32 * i;
            int hd = c4 / 12;
            float4 v = hp[c4], a = ap[c4], dd = dp[c4];
            float s = v.x * a.x + v.y * a.y + v.z * a.z + v.w * a.w;
            float d2 = v.x * dd.x + v.y * dd.y + v.z * dd.z + v.w * dd.w;
            atomicAdd(&sacc[w][hd], s);
            atomicAdd(&sacc[w][8 + hd], d2);
        }
        __syncwarp();
        if (lane < 8)       g_as1[n * 8 + lane] = sacc[w][lane];
        else if (lane < 16) g_ad1[n * 8 + (lane - 8)] = sacc[w][lane];
    }
}

// ---------------- GAT1 single-pass scatter (vector atomics) -------------------
__global__ void scat1k(const int* __restrict__ ei) {
    int gw = (blockIdx.x * blockDim.x + threadIdx.x) >> 5;
    if (gw >= EA) return;
    int lane = threadIdx.x & 31;
    int s, d;
    edge_sd(ei, gw, s, d);
    float ex = 0.f;
    if (lane < 8) {
        float e = leaky(g_as1[s * 8 + lane] + g_ad1[d * 8 + lane]);
        ex = __expf(e);
        atomicAdd(&g_dn1[d * 8 + lane], ex);
    }
    const float4* hs = (const float4*)(g_h1 + (size_t)s * 384);
    float4* nd = (float4*)(g_num1 + (size_t)d * 384);
#pragma unroll
    for (int i = 0; i < 3; i++) {
        int c4 = lane + 32 * i;
        float a = __shfl_sync(0xffffffffu, ex, c4 / 12);
        float4 v = hs[c4];
        atomicAdd(&nd[c4], make_float4(v.x * a, v.y * a, v.z * a, v.w * a));
    }
}

// ---------------- GAT2 ----------------
__global__ void coef2k(const float* __restrict__ asw, const float* __restrict__ adw) {
    int gw = (blockIdx.x * blockDim.x + threadIdx.x) >> 5;
    if (gw >= NN) return;
    int lane = threadIdx.x & 31;
    const float* hp = g_h2 + (size_t)gw * 256;
    float s = 0.f, d = 0.f;
#pragma unroll
    for (int k = 0; k < 8; k++) {
        int c = lane + 32 * k;
        float v = hp[c];
        s += v * asw[c]; d += v * adw[c];
    }
#pragma unroll
    for (int off = 16; off; off >>= 1) {
        s += __shfl_down_sync(0xffffffffu, s, off);
        d += __shfl_down_sync(0xffffffffu, d, off);
    }
    if (lane == 0) { g_as2[gw] = s; g_ad2[gw] = d; }
}

__global__ void scat2k(const int* __restrict__ ei) {
    int gw = (blockIdx.x * blockDim.x + threadIdx.x) >> 5;
    if (gw >= EA) return;
    int lane = threadIdx.x & 31;
    int s, d;
    edge_sd(ei, gw, s, d);
    float ex = 0.f;
    if (lane == 0) {
        ex = __expf(leaky(g_as2[s] + g_ad2[d]));
        atomicAdd(&g_dn2[d], ex);
    }
    ex = __shfl_sync(0xffffffffu, ex, 0);
    const float4* hs = (const float4*)(g_h2 + (size_t)s * 256);
    float4* nd = (float4*)(g_num2 + (size_t)d * 256);
#pragma unroll
    for (int i = 0; i < 2; i++) {
        int c4 = lane + 32 * i;
        float4 v = hs[c4];
        atomicAdd(&nd[c4], make_float4(v.x * ex, v.y * ex, v.z * ex, v.w * ex));
    }
}

// den -> 1/(den+1e-16), in place
__global__ void inv1k() {
    int i = blockIdx.x * blockDim.x + threadIdx.x;
    if (i < NN * 8) g_dn1[i] = 1.f / (g_dn1[i] + 1e-16f);
}
__global__ void inv2k() {
    int i = blockIdx.x * blockDim.x + threadIdx.x;
    if (i < NN) g_dn2[i] = 1.f / (g_dn2[i] + 1e-16f);
}

// ---------------- batch norm (reads normalized num/den on the fly) ------------
__global__ void bnp1() {
    int col = blockIdx.x * 32 + threadIdx.x;
    int hd = col / 48;
    float s = 0.f, q = 0.f;
    for (int r = threadIdx.y + blockIdx.y * 8; r < NN; r += 8 * gridDim.y) {
        float v = g_num1[(size_t)r * 384 + col] * g_dn1[r * 8 + hd];
        s += v; q += v * v;
    }
    __shared__ float sh[8][32], sh2[8][32];
    sh[threadIdx.y][threadIdx.x] = s;
    sh2[threadIdx.y][threadIdx.x] = q;
    __syncthreads();
    if (threadIdx.y == 0) {
#pragma unroll
        for (int y = 1; y < 8; y++) { s += sh[y][threadIdx.x]; q += sh2[y][threadIdx.x]; }
        atomicAdd(&g_sum1[col], s);
        atomicAdd(&g_ss1[col], q);
    }
}
__global__ void bnp2() {
    int col = blockIdx.x * 32 + threadIdx.x;
    float s = 0.f, q = 0.f;
    for (int r = threadIdx.y + blockIdx.y * 8; r < NN; r += 8 * gridDim.y) {
        float v = g_num2[(size_t)r * 256 + col] * g_dn2[r];
        s += v; q += v * v;
    }
    __shared__ float sh[8][32], sh2[8][32];
    sh[threadIdx.y][threadIdx.x] = s;
    sh2[threadIdx.y][threadIdx.x] = q;
    __syncthreads();
    if (threadIdx.y == 0) {
#pragma unroll
        for (int y = 1; y < 8; y++) { s += sh[y][threadIdx.x]; q += sh2[y][threadIdx.x]; }
        atomicAdd(&g_sum2[col], s);
        atomicAdd(&g_ss2[col], q);
    }
}

__global__ void bn_final(int C, const float* __restrict__ sum, const float* __restrict__ ss,
                         float* __restrict__ mu, float* __restrict__ rs) {
    int c = blockIdx.x * blockDim.x + threadIdx.x;
    if (c >= C) return;
    float m = sum[c] * (1.f / NN);
    float v = ss[c] * (1.f / NN) - m * m;
    mu[c] = m;
    rs[c] = rsqrtf(v + 1e-5f);
}

// hr = relu(residual + (num/den - mu)*rstd*gamma + beta)
__global__ void fuse1k(const float* __restrict__ x,
                       const float* __restrict__ g, const float* __restrict__ b) {
    int idx = blockIdx.x * blockDim.x + threadIdx.x;
    if (idx >= NN * 384) return;
    int c = idx % 384;
    int r = idx / 384;
    float val = g_num1[idx] * g_dn1[r * 8 + c / 48];
    val = (val - g_mu1[c]) * g_rs1[c] * g[c] + b[c];
    float h = x[idx] + val;
    g_hr1[idx] = h > 0.f ? h : 0.f;
}
__global__ void fuse2k(const float* __restrict__ g, const float* __restrict__ b) {
    int idx = blockIdx.x * blockDim.x + threadIdx.x;
    if (idx >= NN * 256) return;
    int c = idx & 255;
    int r = idx >> 8;
    float val = g_num2[idx] * g_dn2[r];
    val = (val - g_mu2[c]) * g_rs2[c] * g[c] + b[c];
    float h = g_h5[idx] + val;
    g_hr2[idx] = h > 0.f ? h : 0.f;
}

// ---------------- pair head ----------------
__global__ void pairk(const int* __restrict__ ei, const int* __restrict__ tid,
                      const float* __restrict__ w4, const float* __restrict__ b4,
                      float* __restrict__ out) {
    int gw = (blockIdx.x * blockDim.x + threadIdx.x) >> 5;
    if (gw >= TEN) return;
    int lane = threadIdx.x & 31;
    int e = tid[gw];
    int s = ei[e], d = ei[EE + e];
    const float* hs = g_hf + (size_t)s * 256;
    const float* hd = g_hf + (size_t)d * 256;
    float acc[7] = {};
#pragma unroll
    for (int k = 0; k < 8; k++) {
        int c = lane + 32 * k;
        float p = hs[c] * hd[c];
        const float* wr = &w4[c * 7];
#pragma unroll
        for (int j = 0; j < 7; j++) acc[j] += p * wr[j];
    }
#pragma unroll
    for (int j = 0; j < 7; j++)
#pragma unroll
        for (int off = 16; off; off >>= 1)
            acc[j] += __shfl_down_sync(0xffffffffu, acc[j], off);
    if (lane == 0) {
#pragma unroll
        for (int j = 0; j < 7; j++) out[(size_t)gw * 7 + j] = acc[j] + b4[j];
    }
}

// ---------------- launch ----------------
extern "C" void kernel_launch(void* const* d_in, const int* in_sizes, int n_in,
                              void* d_out, int out_size) {
    const float* x       = (const float*)d_in[0];
    const int*   ei      = (const int*)d_in[1];
    const int*   teid    = (const int*)d_in[2];
    const float* fc1_w   = (const float*)d_in[3];
    const float* fc1_b   = (const float*)d_in[4];
    const float* fc5_w   = (const float*)d_in[5];
    const float* fc5_b   = (const float*)d_in[6];
    const float* fc2_w   = (const float*)d_in[7];
    const float* fc2_b   = (const float*)d_in[8];
    const float* fc4_w   = (const float*)d_in[9];
    const float* fc4_b   = (const float*)d_in[10];
    const float* gat1_w  = (const float*)d_in[11];
    const float* gat1_as = (const float*)d_in[12];
    const float* gat1_ad = (const float*)d_in[13];
    /* gat1_b unused: BN-invariant */
    const float* gat2_w  = (const float*)d_in[15];
    const float* gat2_as = (const float*)d_in[16];
    const float* gat2_ad = (const float*)d_in[17];
    /* gat2_b unused: BN-invariant */
    const float* bn1_g   = (const float*)d_in[19];
    const float* bn1_b   = (const float*)d_in[20];
    const float* bn2_g   = (const float*)d_in[21];
    const float* bn2_b   = (const float*)d_in[22];
    float* out = (float*)d_out;

    float *p_w1c, *p_b1c, *p_h1, *p_hr1, *p_h5, *p_h2, *p_hr2, *p_hf;
    float *p_sum1, *p_ss1, *p_mu1, *p_rs1, *p_sum2, *p_ss2, *p_mu2, *p_rs2;
    cudaGetSymbolAddress((void**)&p_w1c, g_w1c);
    cudaGetSymbolAddress((void**)&p_b1c, g_b1c);
    cudaGetSymbolAddress((void**)&p_h1, g_h1);
    cudaGetSymbolAddress((void**)&p_hr1, g_hr1);
    cudaGetSymbolAddress((void**)&p_h5, g_h5);
    cudaGetSymbolAddress((void**)&p_h2, g_h2);
    cudaGetSymbolAddress((void**)&p_hr2, g_hr2);
    cudaGetSymbolAddress((void**)&p_hf, g_hf);
    cudaGetSymbolAddress((void**)&p_sum1, g_sum1);
    cudaGetSymbolAddress((void**)&p_ss1, g_ss1);
    cudaGetSymbolAddress((void**)&p_mu1, g_mu1);
    cudaGetSymbolAddress((void**)&p_rs1, g_rs1);
    cudaGetSymbolAddress((void**)&p_sum2, g_sum2);
    cudaGetSymbolAddress((void**)&p_ss2, g_ss2);
    cudaGetSymbolAddress((void**)&p_mu2, g_mu2);
    cudaGetSymbolAddress((void**)&p_rs2, g_rs2);

    const int MB = (NN + 127) / 128;  // 79

    // weight fusion: w1c = fc1_w @ gat1_w ; b1c = fc1_b @ gat1_w
    gemm64<<<dim3(6, 6), dim3(16, 16)>>>(fc1_w, gat1_w, nullptr, p_w1c, 384, 384, 384);
    biascomb<<<3, 128>>>(fc1_b, gat1_w);
    init1k<<<(NN * 384 + 255) / 256, 256>>>();

    // h1 = x @ w1c + b1c  (TF32)
    gemm_tf32<<<dim3(3, MB), 256>>>(x, p_w1c, p_b1c, p_h1, NN, 384, 384);

    coef1k<<<(NN + 7) / 8, 256>>>(gat1_as, gat1_ad);
    scat1k<<<(EA * 32 + 255) / 256, 256>>>(ei);
    inv1k<<<(NN * 8 + 255) / 256, 256>>>();

    bnp1<<<dim3(12, 16), dim3(32, 8)>>>();
    bn_final<<<2, 256>>>(384, p_sum1, p_ss1, p_mu1, p_rs1);
    fuse1k<<<(NN * 384 + 255) / 256, 256>>>(x, bn1_g, bn1_b);

    // h5 = hr1 @ fc5_w + fc5_b ; h2 = h5 @ gat2_w  (TF32)
    gemm_tf32<<<dim3(2, MB), 256>>>(p_hr1, fc5_w, fc5_b, p_h5, NN, 384, 256);
    init2k<<<(NN * 256 + 255) / 256, 256>>>();
    gemm_tf32<<<dim3(2, MB), 256>>>(p_h5, gat2_w, nullptr, p_h2, NN, 256, 256);

    coef2k<<<(NN * 32 + 255) / 256, 256>>>(gat2_as, gat2_ad);
    scat2k<<<(EA * 32 + 255) / 256, 256>>>(ei);
    inv2k<<<(NN + 255) / 256, 256>>>();

    bnp2<<<dim3(8, 16), dim3(32, 8)>>>();
    bn_final<<<1, 256>>>(256, p_sum2, p_ss2, p_mu2, p_rs2);
    fuse2k<<<(NN * 256 + 255) / 256, 256>>>(bn2_g, bn2_b);

    // hf = hr2 @ fc2_w + fc2_b  (TF32)
    gemm_tf32<<<dim3(2, MB), 256>>>(p_hr2, fc2_w, fc2_b, p_hf, NN, 256, 256);

    // pair head
    pairk<<<(TEN * 32 + 255) / 256, 256>>>(ei, teid, fc4_w, fc4_b, out);
}